// round 1
// baseline (speedup 1.0000x reference)
#include <cuda_runtime.h>
#include <math.h>

// ---------------- problem constants ----------------
#define NI      16          // instances = N_CLASSES(2) * B(8)
#define HW      409600      // 640*640
#define HW4     102400      // HW/4
#define NCH     12
#define NMAPS   6
#define EPSF    1e-4
#define BPI     9           // blocks per instance for scan passes (16*9=144 ~ 1 wave)
#define DB      56          // blocks per instance for dice pass (16*56=896 blocks)

// ---------------- device scratch (static; no runtime allocation) ----------------
__device__ unsigned g_pos[NI];
__device__ unsigned g_neg[NI];
__device__ unsigned g_minkey[NI];
__device__ unsigned g_maxkey[NI];
__device__ int      g_mode[NI];       // 0 = resolved (thr ready / fallback), 1 = needs histogram path
__device__ int      g_fallback[NI];
__device__ float    g_thr[NI];
__device__ int      g_anyhist;
__device__ unsigned g_selhi[NI];
__device__ unsigned g_krem[NI];
__device__ unsigned g_histhi[NI][8192];       // top-13-bit histogram (rare path)
__device__ unsigned g_histlo[NI][524288];     // low-19-bit histogram (rare path)
__device__ double   g_sums[NI][18];           // [0..2]=text a,b,c ; [3+j]=a_kj ; [8+j]=b_kj ; [13+j]=c_kj

// order-preserving float->uint key (larger float => larger key)
__device__ __forceinline__ unsigned keyOf(float x) {
    unsigned u = __float_as_uint(x);
    return (u & 0x80000000u) ? ~u : (u | 0x80000000u);
}
__device__ __forceinline__ float unkey(unsigned k) {
    unsigned u = (k & 0x80000000u) ? (k ^ 0x80000000u) : ~k;
    return __uint_as_float(u);
}

// ---------------- kernel 1: clear small scratch ----------------
__global__ void k_clear() {
    int t = threadIdx.x;
    if (t < NI) {
        g_pos[t] = 0u; g_neg[t] = 0u;
        g_minkey[t] = 0xFFFFFFFFu; g_maxkey[t] = 0u;
        g_mode[t] = 0; g_fallback[t] = 0; g_thr[t] = 0.f;
    }
    if (t == 0) g_anyhist = 0;
    double* s = &g_sums[0][0];
    for (int i = t; i < NI * 18; i += blockDim.x) s[i] = 0.0;
}

// ---------------- kernel 2: fused count (pos/neg) + min/max negative key ----------------
__global__ void k_count(const float* __restrict__ outs,
                        const float* __restrict__ labs,
                        const float* __restrict__ tmg) {
    int inst = blockIdx.x / BPI;
    int cb   = blockIdx.x % BPI;
    int i = inst >> 3, b = inst & 7;
    int ch = i * NMAPS + (NMAPS - 1);
    const float4* sc4 = (const float4*)(outs + ((size_t)b * NCH + ch) * HW);
    const float4* gt4 = (const float4*)(labs + ((size_t)b * NCH + ch) * HW);
    const float4* m4  = (const float4*)(tmg + (size_t)b * HW);

    unsigned pos = 0, neg = 0, mink = 0xFFFFFFFFu, maxk = 0u;
    for (int idx = cb * blockDim.x + threadIdx.x; idx < HW4; idx += BPI * blockDim.x) {
        float4 s = sc4[idx]; float4 g = gt4[idx]; float4 m = m4[idx];
        float sv[4] = {s.x, s.y, s.z, s.w};
        float gv[4] = {g.x, g.y, g.z, g.w};
        float mv[4] = {m.x, m.y, m.z, m.w};
        #pragma unroll
        for (int e = 0; e < 4; e++) {
            if (gv[e] > 0.5f && mv[e] > 0.5f) pos++;
            if (gv[e] <= 0.5f) {
                neg++;
                unsigned kk = keyOf(sv[e]);
                mink = min(mink, kk);
                maxk = max(maxk, kk);
            }
        }
    }
    #pragma unroll
    for (int o = 16; o; o >>= 1) {
        pos += __shfl_down_sync(0xffffffffu, pos, o);
        neg += __shfl_down_sync(0xffffffffu, neg, o);
        mink = min(mink, __shfl_down_sync(0xffffffffu, mink, o));
        maxk = max(maxk, __shfl_down_sync(0xffffffffu, maxk, o));
    }
    __shared__ unsigned spos, sneg, smin, smax;
    if (threadIdx.x == 0) { spos = 0u; sneg = 0u; smin = 0xFFFFFFFFu; smax = 0u; }
    __syncthreads();
    if ((threadIdx.x & 31) == 0) {
        atomicAdd(&spos, pos); atomicAdd(&sneg, neg);
        atomicMin(&smin, mink); atomicMax(&smax, maxk);
    }
    __syncthreads();
    if (threadIdx.x == 0) {
        atomicAdd(&g_pos[inst], spos); atomicAdd(&g_neg[inst], sneg);
        atomicMin(&g_minkey[inst], smin); atomicMax(&g_maxkey[inst], smax);
    }
}

// ---------------- kernel 3: decide k / fallback / fast-path threshold ----------------
__global__ void k_decide() {
    int t = threadIdx.x;
    if (t >= NI) return;
    unsigned pos = g_pos[t], neg = g_neg[t];
    unsigned long long k = min((unsigned long long)pos * 3ull, (unsigned long long)neg);
    if (pos == 0u || k == 0ull) {
        g_fallback[t] = 1; g_mode[t] = 0; g_thr[t] = 0.f;
        return;
    }
    g_fallback[t] = 0;
    if (k == (unsigned long long)neg) {        // select ALL negatives -> thr = min negative
        g_thr[t] = unkey(g_minkey[t]); g_mode[t] = 0;
    } else if (k == 1ull) {                    // thr = max negative
        g_thr[t] = unkey(g_maxkey[t]); g_mode[t] = 0;
    } else {                                   // rare: exact radix select needed
        g_mode[t] = 1;
        atomicExch(&g_anyhist, 1);
    }
}

// ---------------- kernel 4 (guarded): clear histograms ----------------
__global__ void k_clearhist() {
    if (g_anyhist == 0) return;
    unsigned* hi = &g_histhi[0][0];
    unsigned* lo = &g_histlo[0][0];
    size_t nhi = (size_t)NI * 8192, nlo = (size_t)NI * 524288;
    size_t stride = (size_t)gridDim.x * blockDim.x;
    for (size_t idx = (size_t)blockIdx.x * blockDim.x + threadIdx.x; idx < nhi; idx += stride) hi[idx] = 0u;
    for (size_t idx = (size_t)blockIdx.x * blockDim.x + threadIdx.x; idx < nlo; idx += stride) lo[idx] = 0u;
}

// ---------------- kernel 5 (guarded): top-13-bit histogram of negative keys ----------------
__global__ void k_histhi(const float* __restrict__ outs, const float* __restrict__ labs) {
    int inst = blockIdx.x / BPI;
    if (g_mode[inst] != 1) return;
    int cb = blockIdx.x % BPI;
    int i = inst >> 3, b = inst & 7;
    int ch = i * NMAPS + (NMAPS - 1);
    const float4* sc4 = (const float4*)(outs + ((size_t)b * NCH + ch) * HW);
    const float4* gt4 = (const float4*)(labs + ((size_t)b * NCH + ch) * HW);

    __shared__ unsigned sh[8192];
    for (int j = threadIdx.x; j < 8192; j += blockDim.x) sh[j] = 0u;
    __syncthreads();
    for (int idx = cb * blockDim.x + threadIdx.x; idx < HW4; idx += BPI * blockDim.x) {
        float4 s = sc4[idx]; float4 g = gt4[idx];
        float sv[4] = {s.x, s.y, s.z, s.w};
        float gv[4] = {g.x, g.y, g.z, g.w};
        #pragma unroll
        for (int e = 0; e < 4; e++)
            if (gv[e] <= 0.5f) atomicAdd(&sh[keyOf(sv[e]) >> 19], 1u);
    }
    __syncthreads();
    for (int j = threadIdx.x; j < 8192; j += blockDim.x) {
        unsigned c = sh[j];
        if (c) atomicAdd(&g_histhi[inst][j], c);
    }
}

// ---------------- kernel 6 (guarded): scan hi histogram descending ----------------
__global__ void k_scanhi() {
    int inst = blockIdx.x;
    if (g_mode[inst] != 1) return;
    __shared__ unsigned long long csum[1024];
    int t = threadIdx.x;
    // chunk t covers bins [8192-(t+1)*8, 8192-t*8) in descending order
    unsigned long long s = 0;
    int hi = 8192 - t * 8;
    for (int bn = hi - 1; bn >= hi - 8; bn--) s += g_histhi[inst][bn];
    csum[t] = s;
    __syncthreads();
    if (t == 0) {
        unsigned long long k = min((unsigned long long)g_pos[inst] * 3ull,
                                   (unsigned long long)g_neg[inst]);
        unsigned long long cum = 0;
        for (int c = 0; c < 1024; c++) {
            if (cum + csum[c] >= k) {
                int h2 = 8192 - c * 8;
                for (int bn = h2 - 1; bn >= h2 - 8; bn--) {
                    unsigned long long hv = g_histhi[inst][bn];
                    if (cum + hv >= k) {
                        g_selhi[inst] = (unsigned)bn;
                        g_krem[inst]  = (unsigned)(k - cum);
                        return;
                    }
                    cum += hv;
                }
            }
            cum += csum[c];
        }
    }
}

// ---------------- kernel 7 (guarded): low-19-bit histogram of matching keys ----------------
__global__ void k_histlo(const float* __restrict__ outs, const float* __restrict__ labs) {
    int inst = blockIdx.x / BPI;
    if (g_mode[inst] != 1) return;
    int cb = blockIdx.x % BPI;
    int i = inst >> 3, b = inst & 7;
    int ch = i * NMAPS + (NMAPS - 1);
    const float4* sc4 = (const float4*)(outs + ((size_t)b * NCH + ch) * HW);
    const float4* gt4 = (const float4*)(labs + ((size_t)b * NCH + ch) * HW);
    unsigned sel = g_selhi[inst];
    for (int idx = cb * blockDim.x + threadIdx.x; idx < HW4; idx += BPI * blockDim.x) {
        float4 s = sc4[idx]; float4 g = gt4[idx];
        float sv[4] = {s.x, s.y, s.z, s.w};
        float gv[4] = {g.x, g.y, g.z, g.w};
        #pragma unroll
        for (int e = 0; e < 4; e++) {
            if (gv[e] <= 0.5f) {
                unsigned kk = keyOf(sv[e]);
                if ((kk >> 19) == sel) atomicAdd(&g_histlo[inst][kk & 0x7FFFFu], 1u);
            }
        }
    }
}

// ---------------- kernel 8 (guarded): scan lo histogram -> exact threshold ----------------
__global__ void k_scanlo() {
    int inst = blockIdx.x;
    if (g_mode[inst] != 1) return;
    __shared__ unsigned long long csum[1024];
    int t = threadIdx.x;
    unsigned long long s = 0;
    int hi = 524288 - t * 512;
    for (int bn = hi - 1; bn >= hi - 512; bn--) s += g_histlo[inst][bn];
    csum[t] = s;
    __syncthreads();
    if (t == 0) {
        unsigned long long k = (unsigned long long)g_krem[inst];
        unsigned sel = g_selhi[inst];
        unsigned long long cum = 0;
        for (int c = 0; c < 1024; c++) {
            if (cum + csum[c] >= k) {
                int h2 = 524288 - c * 512;
                for (int bn = h2 - 1; bn >= h2 - 512; bn--) {
                    unsigned long long hv = g_histlo[inst][bn];
                    if (cum + hv >= k) {
                        unsigned key = (sel << 19) | (unsigned)bn;
                        g_thr[inst] = unkey(key);
                        return;
                    }
                    cum += hv;
                }
            }
            cum += csum[c];
        }
    }
}

// ---------------- kernel 9: fused dice reductions ----------------
__global__ void __launch_bounds__(256) k_dice(const float* __restrict__ outs,
                                              const float* __restrict__ labs,
                                              const float* __restrict__ tmg) {
    int inst = blockIdx.x / DB;
    int cb   = blockIdx.x % DB;
    int i = inst >> 3, b = inst & 7;
    const float thr = g_thr[inst];
    const int   fb  = g_fallback[inst];

    const float4* tx4 = (const float4*)(outs + ((size_t)b * NCH + i * NMAPS + 5) * HW);
    const float4* gt4 = (const float4*)(labs + ((size_t)b * NCH + i * NMAPS + 5) * HW);
    const float4* m4  = (const float4*)(tmg + (size_t)b * HW);
    const float4* kv4[5];
    const float4* gk4[5];
    #pragma unroll
    for (int j = 0; j < 5; j++) {
        kv4[j] = (const float4*)(outs + ((size_t)b * NCH + i * NMAPS + j) * HW);
        gk4[j] = (const float4*)(labs + ((size_t)b * NCH + i * NMAPS + j) * HW);
    }

    float acc[18];
    #pragma unroll
    for (int j = 0; j < 18; j++) acc[j] = 0.f;

    for (int idx = cb * 256 + threadIdx.x; idx < HW4; idx += DB * 256) {
        float4 t = tx4[idx]; float4 g = gt4[idx]; float4 m = m4[idx];
        float tv[4] = {t.x, t.y, t.z, t.w};
        float gv[4] = {g.x, g.y, g.z, g.w};
        float mv[4] = {m.x, m.y, m.z, m.w};
        float selk[4];
        #pragma unroll
        for (int e = 0; e < 4; e++) {
            float sc = tv[e], gval = gv[e], mval = mv[e];
            float st = fb ? mval
                          : (((sc >= thr) || (gval > 0.5f)) && (mval > 0.5f) ? 1.f : 0.f);
            float sg = __fdividef(1.f, 1.f + __expf(-sc));
            float p = sg * st, tt = gval * st;
            acc[0] = fmaf(p, tt, acc[0]);
            acc[1] = fmaf(p, p,  acc[1]);
            acc[2] = fmaf(tt, tt, acc[2]);
            selk[e] = (sc > 0.f && mval > 0.5f) ? 1.f : 0.f;
        }
        #pragma unroll
        for (int j = 0; j < 5; j++) {
            float4 kv = kv4[j][idx];
            float4 gk = gk4[j][idx];
            float kvv[4] = {kv.x, kv.y, kv.z, kv.w};
            float gkk[4] = {gk.x, gk.y, gk.z, gk.w};
            #pragma unroll
            for (int e = 0; e < 4; e++) {
                float sg = __fdividef(1.f, 1.f + __expf(-kvv[e]));
                float p = sg * selk[e], tt = gkk[e] * selk[e];
                acc[3 + j]  = fmaf(p, tt, acc[3 + j]);
                acc[8 + j]  = fmaf(p, p,  acc[8 + j]);
                acc[13 + j] = fmaf(tt, tt, acc[13 + j]);
            }
        }
    }

    // warp reduce all 18
    #pragma unroll
    for (int j = 0; j < 18; j++) {
        float v = acc[j];
        #pragma unroll
        for (int o = 16; o; o >>= 1) v += __shfl_down_sync(0xffffffffu, v, o);
        acc[j] = v;
    }
    __shared__ float bsum[18];
    if (threadIdx.x < 18) bsum[threadIdx.x] = 0.f;
    __syncthreads();
    if ((threadIdx.x & 31) == 0) {
        #pragma unroll
        for (int j = 0; j < 18; j++) atomicAdd(&bsum[j], acc[j]);
    }
    __syncthreads();
    if (threadIdx.x < 18) atomicAdd(&g_sums[inst][threadIdx.x], (double)bsum[threadIdx.x]);
}

// ---------------- kernel 10: finalize 3 outputs ----------------
__global__ void k_final(float* __restrict__ out) {
    __shared__ double slt[NI], slk[NI];
    int t = threadIdx.x;
    if (t < NI) {
        double a  = g_sums[t][0];
        double bb = g_sums[t][1] + EPSF;
        double cc = g_sums[t][2] + EPSF;
        double lt = 1.0 - 2.0 * a / (bb + cc);
        double lk = 0.0;
        for (int j = 0; j < 5; j++) {
            double aj = g_sums[t][3 + j];
            double bj = g_sums[t][8 + j] + EPSF;
            double cj = g_sums[t][13 + j] + EPSF;
            lk += 1.0 - 2.0 * aj / (bj + cj);
        }
        lk *= 0.2;
        slt[t] = lt; slk[t] = lk;
    }
    __syncthreads();
    if (t == 0) {
        double lt0 = 0, lt1 = 0, lk0 = 0, lk1 = 0;
        for (int b2 = 0; b2 < 8; b2++) {
            lt0 += slt[b2];     lk0 += slk[b2];
            lt1 += slt[8 + b2]; lk1 += slk[8 + b2];
        }
        lt0 *= 0.125; lk0 *= 0.125; lt1 *= 0.125; lk1 *= 0.125;
        double l0 = 0.7 * lt0 + 0.3 * lk0;
        double l1 = 0.7 * lt1 + 0.3 * lk1;
        out[0] = (float)(0.5 * (l0 + l1));
        out[1] = (float)(0.5 * (lt0 + lt1));
        out[2] = (float)(0.5 * (lk0 + lk1));
    }
}

// ---------------- launch ----------------
extern "C" void kernel_launch(void* const* d_in, const int* in_sizes, int n_in,
                              void* d_out, int out_size) {
    const float* outs = (const float*)d_in[0];
    const float* labs = (const float*)d_in[1];
    const float* tmg  = (const float*)d_in[2];
    float* out = (float*)d_out;

    k_clear<<<1, 288>>>();
    k_count<<<NI * BPI, 256>>>(outs, labs, tmg);
    k_decide<<<1, 32>>>();
    // rare exact-select path (all blocks early-exit on the fast path)
    k_clearhist<<<256, 1024>>>();
    k_histhi<<<NI * BPI, 512>>>(outs, labs);
    k_scanhi<<<NI, 1024>>>();
    k_histlo<<<NI * BPI, 256>>>(outs, labs);
    k_scanlo<<<NI, 1024>>>();
    // main fused dice pass + finalize
    k_dice<<<NI * DB, 256>>>(outs, labs, tmg);
    k_final<<<1, 32>>>(out);
}

// round 2
// speedup vs baseline: 1.1763x; 1.1763x over previous
#include <cuda_runtime.h>
#include <math.h>

// ---------------- problem constants ----------------
#define NI      16          // instances = N_CLASSES(2) * B(8)
#define HW      409600      // 640*640
#define HW4     102400      // HW/4
#define NCH     12
#define NMAPS   6
#define EPSF    1e-4
#define CB      74          // count blocks per batch image (8*74 = 592 blocks)
#define BPI     9           // blocks per instance for guarded hist passes
#define DB      56          // blocks per instance for dice pass (16*56=896 blocks)

// ---------------- device scratch (static; no runtime allocation) ----------------
__device__ unsigned g_pos[NI];
__device__ unsigned g_neg[NI];
__device__ int      g_mode[NI];       // 0 = resolved (thr/fallback ready), 1 = needs histogram path
__device__ int      g_fallback[NI];
__device__ float    g_thr[NI];
__device__ int      g_anyhist;
__device__ unsigned g_selhi[NI];
__device__ unsigned g_krem[NI];
__device__ unsigned g_histhi[NI][8192];       // top-13-bit histogram (rare path)
__device__ unsigned g_histlo[NI][524288];     // low-19-bit histogram (rare path)
__device__ double   g_sums[NI][18];           // [0..2]=text a,b,c ; [3+j]=a_kj ; [8+j]=b_kj ; [13+j]=c_kj

// order-preserving float->uint key (larger float => larger key)
__device__ __forceinline__ unsigned keyOf(float x) {
    unsigned u = __float_as_uint(x);
    return (u & 0x80000000u) ? ~u : (u | 0x80000000u);
}
__device__ __forceinline__ float unkey(unsigned k) {
    unsigned u = (k & 0x80000000u) ? (k ^ 0x80000000u) : ~k;
    return __uint_as_float(u);
}

// ---------------- kernel 1: clear small scratch ----------------
__global__ void k_clear() {
    int t = threadIdx.x;
    if (t < NI) {
        g_pos[t] = 0u; g_neg[t] = 0u;
        g_mode[t] = 0; g_fallback[t] = 0; g_thr[t] = 0.f;
    }
    if (t == 0) g_anyhist = 0;
    double* s = &g_sums[0][0];
    for (int i = t; i < NI * 18; i += blockDim.x) s[i] = 0.0;
}

// ---------------- kernel 2: pos/neg counts (gt_text + tm only; both classes per block) ----------------
__global__ void __launch_bounds__(256) k_count(const float* __restrict__ labs,
                                               const float* __restrict__ tmg) {
    int b  = blockIdx.x / CB;
    int cb = blockIdx.x % CB;
    const float4* g0 = (const float4*)labs + ((size_t)b * NCH + 5)  * HW4;
    const float4* g1 = (const float4*)labs + ((size_t)b * NCH + 11) * HW4;
    const float4* m4 = (const float4*)tmg  + (size_t)b * HW4;

    unsigned p0 = 0, n0 = 0, p1 = 0, n1 = 0;
    for (int idx = cb * 256 + threadIdx.x; idx < HW4; idx += CB * 256) {
        float4 a = g0[idx]; float4 c = g1[idx]; float4 m = m4[idx];
        float av[4] = {a.x, a.y, a.z, a.w};
        float cv[4] = {c.x, c.y, c.z, c.w};
        float mv[4] = {m.x, m.y, m.z, m.w};
        #pragma unroll
        for (int e = 0; e < 4; e++) {
            bool tm = mv[e] > 0.5f;
            if (av[e] > 0.5f) { if (tm) p0++; } else n0++;
            if (cv[e] > 0.5f) { if (tm) p1++; } else n1++;
        }
    }
    #pragma unroll
    for (int o = 16; o; o >>= 1) {
        p0 += __shfl_down_sync(0xffffffffu, p0, o);
        n0 += __shfl_down_sync(0xffffffffu, n0, o);
        p1 += __shfl_down_sync(0xffffffffu, p1, o);
        n1 += __shfl_down_sync(0xffffffffu, n1, o);
    }
    __shared__ unsigned sp0, sn0, sp1, sn1;
    if (threadIdx.x == 0) { sp0 = sn0 = sp1 = sn1 = 0u; }
    __syncthreads();
    if ((threadIdx.x & 31) == 0) {
        atomicAdd(&sp0, p0); atomicAdd(&sn0, n0);
        atomicAdd(&sp1, p1); atomicAdd(&sn1, n1);
    }
    __syncthreads();
    if (threadIdx.x == 0) {
        atomicAdd(&g_pos[b],     sp0); atomicAdd(&g_neg[b],     sn0);
        atomicAdd(&g_pos[8 + b], sp1); atomicAdd(&g_neg[8 + b], sn1);
    }
}

// ---------------- kernel 3: decide fallback / select-all / histogram path ----------------
__global__ void k_decide() {
    int t = threadIdx.x;
    if (t >= NI) return;
    unsigned pos = g_pos[t], neg = g_neg[t];
    unsigned long long k = min((unsigned long long)pos * 3ull, (unsigned long long)neg);
    if (pos == 0u || k == 0ull) {
        g_fallback[t] = 1; g_mode[t] = 0; g_thr[t] = 0.f;
    } else if (k == (unsigned long long)neg) {
        // all negatives selected -> sel == (tm>0.5) regardless of threshold value
        g_fallback[t] = 0; g_mode[t] = 0; g_thr[t] = -INFINITY;
    } else {
        g_fallback[t] = 0; g_mode[t] = 1;
        atomicExch(&g_anyhist, 1);
    }
}

// ---------------- kernel 4 (guarded): clear histograms ----------------
__global__ void k_clearhist() {
    if (g_anyhist == 0) return;
    unsigned* hi = &g_histhi[0][0];
    unsigned* lo = &g_histlo[0][0];
    size_t nhi = (size_t)NI * 8192, nlo = (size_t)NI * 524288;
    size_t stride = (size_t)gridDim.x * blockDim.x;
    for (size_t idx = (size_t)blockIdx.x * blockDim.x + threadIdx.x; idx < nhi; idx += stride) hi[idx] = 0u;
    for (size_t idx = (size_t)blockIdx.x * blockDim.x + threadIdx.x; idx < nlo; idx += stride) lo[idx] = 0u;
}

// ---------------- kernel 5 (guarded): top-13-bit histogram of negative keys ----------------
__global__ void k_histhi(const float* __restrict__ outs, const float* __restrict__ labs) {
    int inst = blockIdx.x / BPI;
    if (g_mode[inst] != 1) return;
    int cb = blockIdx.x % BPI;
    int i = inst >> 3, b = inst & 7;
    int ch = i * NMAPS + (NMAPS - 1);
    const float4* sc4 = (const float4*)outs + ((size_t)b * NCH + ch) * HW4;
    const float4* gt4 = (const float4*)labs + ((size_t)b * NCH + ch) * HW4;

    __shared__ unsigned sh[8192];
    for (int j = threadIdx.x; j < 8192; j += blockDim.x) sh[j] = 0u;
    __syncthreads();
    for (int idx = cb * blockDim.x + threadIdx.x; idx < HW4; idx += BPI * blockDim.x) {
        float4 s = sc4[idx]; float4 g = gt4[idx];
        float sv[4] = {s.x, s.y, s.z, s.w};
        float gv[4] = {g.x, g.y, g.z, g.w};
        #pragma unroll
        for (int e = 0; e < 4; e++)
            if (gv[e] <= 0.5f) atomicAdd(&sh[keyOf(sv[e]) >> 19], 1u);
    }
    __syncthreads();
    for (int j = threadIdx.x; j < 8192; j += blockDim.x) {
        unsigned c = sh[j];
        if (c) atomicAdd(&g_histhi[inst][j], c);
    }
}

// ---------------- kernel 6 (guarded): scan hi histogram descending ----------------
__global__ void k_scanhi() {
    int inst = blockIdx.x;
    if (g_mode[inst] != 1) return;
    __shared__ unsigned long long csum[1024];
    int t = threadIdx.x;
    unsigned long long s = 0;
    int hi = 8192 - t * 8;
    for (int bn = hi - 1; bn >= hi - 8; bn--) s += g_histhi[inst][bn];
    csum[t] = s;
    __syncthreads();
    if (t == 0) {
        unsigned long long k = min((unsigned long long)g_pos[inst] * 3ull,
                                   (unsigned long long)g_neg[inst]);
        unsigned long long cum = 0;
        for (int c = 0; c < 1024; c++) {
            if (cum + csum[c] >= k) {
                int h2 = 8192 - c * 8;
                for (int bn = h2 - 1; bn >= h2 - 8; bn--) {
                    unsigned long long hv = g_histhi[inst][bn];
                    if (cum + hv >= k) {
                        g_selhi[inst] = (unsigned)bn;
                        g_krem[inst]  = (unsigned)(k - cum);
                        return;
                    }
                    cum += hv;
                }
            }
            cum += csum[c];
        }
    }
}

// ---------------- kernel 7 (guarded): low-19-bit histogram of matching keys ----------------
__global__ void k_histlo(const float* __restrict__ outs, const float* __restrict__ labs) {
    int inst = blockIdx.x / BPI;
    if (g_mode[inst] != 1) return;
    int cb = blockIdx.x % BPI;
    int i = inst >> 3, b = inst & 7;
    int ch = i * NMAPS + (NMAPS - 1);
    const float4* sc4 = (const float4*)outs + ((size_t)b * NCH + ch) * HW4;
    const float4* gt4 = (const float4*)labs + ((size_t)b * NCH + ch) * HW4;
    unsigned sel = g_selhi[inst];
    for (int idx = cb * blockDim.x + threadIdx.x; idx < HW4; idx += BPI * blockDim.x) {
        float4 s = sc4[idx]; float4 g = gt4[idx];
        float sv[4] = {s.x, s.y, s.z, s.w};
        float gv[4] = {g.x, g.y, g.z, g.w};
        #pragma unroll
        for (int e = 0; e < 4; e++) {
            if (gv[e] <= 0.5f) {
                unsigned kk = keyOf(sv[e]);
                if ((kk >> 19) == sel) atomicAdd(&g_histlo[inst][kk & 0x7FFFFu], 1u);
            }
        }
    }
}

// ---------------- kernel 8 (guarded): scan lo histogram -> exact threshold ----------------
__global__ void k_scanlo() {
    int inst = blockIdx.x;
    if (g_mode[inst] != 1) return;
    __shared__ unsigned long long csum[1024];
    int t = threadIdx.x;
    unsigned long long s = 0;
    int hi = 524288 - t * 512;
    for (int bn = hi - 1; bn >= hi - 512; bn--) s += g_histlo[inst][bn];
    csum[t] = s;
    __syncthreads();
    if (t == 0) {
        unsigned long long k = (unsigned long long)g_krem[inst];
        unsigned sel = g_selhi[inst];
        unsigned long long cum = 0;
        for (int c = 0; c < 1024; c++) {
            if (cum + csum[c] >= k) {
                int h2 = 524288 - c * 512;
                for (int bn = h2 - 1; bn >= h2 - 512; bn--) {
                    unsigned long long hv = g_histlo[inst][bn];
                    if (cum + hv >= k) {
                        unsigned key = (sel << 19) | (unsigned)bn;
                        g_thr[inst] = unkey(key);
                        return;
                    }
                    cum += hv;
                }
            }
            cum += csum[c];
        }
    }
}

// ---------------- kernel 9: fused dice reductions ----------------
// inst order interleaves classes so (class0,b) and (class1,b) run adjacently -> tm L2 reuse
__global__ void __launch_bounds__(256) k_dice(const float* __restrict__ outs,
                                              const float* __restrict__ labs,
                                              const float* __restrict__ tmg) {
    int inst = blockIdx.x / DB;
    int cb   = blockIdx.x % DB;
    int b = inst >> 1, i = inst & 1;
    int iid = i * 8 + b;
    const float thr = g_thr[iid];
    const int   fb  = g_fallback[iid];

    const float4* ob = (const float4*)outs + ((size_t)b * NCH + i * NMAPS) * HW4;
    const float4* lb = (const float4*)labs + ((size_t)b * NCH + i * NMAPS) * HW4;
    const float4* m4 = (const float4*)tmg  + (size_t)b * HW4;

    float acc[18];
    #pragma unroll
    for (int j = 0; j < 18; j++) acc[j] = 0.f;

    for (int idx = cb * 256 + threadIdx.x; idx < HW4; idx += DB * 256) {
        float4 t = ob[5 * HW4 + idx];
        float4 g = lb[5 * HW4 + idx];
        float4 m = m4[idx];
        float tv[4] = {t.x, t.y, t.z, t.w};
        float gv[4] = {g.x, g.y, g.z, g.w};
        float mv[4] = {m.x, m.y, m.z, m.w};
        float selk[4];
        #pragma unroll
        for (int e = 0; e < 4; e++) {
            float sc = tv[e], gval = gv[e], mval = mv[e];
            float st = fb ? mval
                          : (((sc >= thr) || (gval > 0.5f)) && (mval > 0.5f) ? 1.f : 0.f);
            float sg = __fdividef(1.f, 1.f + __expf(-sc));
            float p = sg * st, tt = gval * st;
            acc[0] = fmaf(p, tt, acc[0]);
            acc[1] = fmaf(p, p,  acc[1]);
            acc[2] = fmaf(tt, tt, acc[2]);
            selk[e] = (sc > 0.f && mval > 0.5f) ? 1.f : 0.f;
        }
        #pragma unroll
        for (int j = 0; j < 5; j++) {
            float4 kv = ob[(size_t)j * HW4 + idx];
            float4 gk = lb[(size_t)j * HW4 + idx];
            float kvv[4] = {kv.x, kv.y, kv.z, kv.w};
            float gkk[4] = {gk.x, gk.y, gk.z, gk.w};
            #pragma unroll
            for (int e = 0; e < 4; e++) {
                float sg = __fdividef(1.f, 1.f + __expf(-kvv[e]));
                float p = sg * selk[e], tt = gkk[e] * selk[e];
                acc[3 + j]  = fmaf(p, tt, acc[3 + j]);
                acc[8 + j]  = fmaf(p, p,  acc[8 + j]);
                acc[13 + j] = fmaf(tt, tt, acc[13 + j]);
            }
        }
    }

    #pragma unroll
    for (int j = 0; j < 18; j++) {
        float v = acc[j];
        #pragma unroll
        for (int o = 16; o; o >>= 1) v += __shfl_down_sync(0xffffffffu, v, o);
        acc[j] = v;
    }
    __shared__ float bsum[18];
    if (threadIdx.x < 18) bsum[threadIdx.x] = 0.f;
    __syncthreads();
    if ((threadIdx.x & 31) == 0) {
        #pragma unroll
        for (int j = 0; j < 18; j++) atomicAdd(&bsum[j], acc[j]);
    }
    __syncthreads();
    if (threadIdx.x < 18) atomicAdd(&g_sums[iid][threadIdx.x], (double)bsum[threadIdx.x]);
}

// ---------------- kernel 10: finalize 3 outputs ----------------
__global__ void k_final(float* __restrict__ out) {
    __shared__ double slt[NI], slk[NI];
    int t = threadIdx.x;
    if (t < NI) {
        double a  = g_sums[t][0];
        double bb = g_sums[t][1] + EPSF;
        double cc = g_sums[t][2] + EPSF;
        double lt = 1.0 - 2.0 * a / (bb + cc);
        double lk = 0.0;
        for (int j = 0; j < 5; j++) {
            double aj = g_sums[t][3 + j];
            double bj = g_sums[t][8 + j] + EPSF;
            double cj = g_sums[t][13 + j] + EPSF;
            lk += 1.0 - 2.0 * aj / (bj + cj);
        }
        lk *= 0.2;
        slt[t] = lt; slk[t] = lk;
    }
    __syncthreads();
    if (t == 0) {
        double lt0 = 0, lt1 = 0, lk0 = 0, lk1 = 0;
        for (int b2 = 0; b2 < 8; b2++) {
            lt0 += slt[b2];     lk0 += slk[b2];
            lt1 += slt[8 + b2]; lk1 += slk[8 + b2];
        }
        lt0 *= 0.125; lk0 *= 0.125; lt1 *= 0.125; lk1 *= 0.125;
        double l0 = 0.7 * lt0 + 0.3 * lk0;
        double l1 = 0.7 * lt1 + 0.3 * lk1;
        out[0] = (float)(0.5 * (l0 + l1));
        out[1] = (float)(0.5 * (lt0 + lt1));
        out[2] = (float)(0.5 * (lk0 + lk1));
    }
}

// ---------------- launch ----------------
extern "C" void kernel_launch(void* const* d_in, const int* in_sizes, int n_in,
                              void* d_out, int out_size) {
    const float* outs = (const float*)d_in[0];
    const float* labs = (const float*)d_in[1];
    const float* tmg  = (const float*)d_in[2];
    float* out = (float*)d_out;

    k_clear<<<1, 288>>>();
    k_count<<<8 * CB, 256>>>(labs, tmg);
    k_decide<<<1, 32>>>();
    // rare exact-select path (all blocks early-exit on the fast path)
    k_clearhist<<<64, 256>>>();
    k_histhi<<<NI * BPI, 512>>>(outs, labs);
    k_scanhi<<<NI, 1024>>>();
    k_histlo<<<NI * BPI, 256>>>(outs, labs);
    k_scanlo<<<NI, 1024>>>();
    // main fused dice pass + finalize
    k_dice<<<NI * DB, 256>>>(outs, labs, tmg);
    k_final<<<1, 32>>>(out);
}